// round 7
// baseline (speedup 1.0000x reference)
#include <cuda_runtime.h>
#include <cuda_bf16.h>

// FWHT, N = 4096, fp32, Sylvester ordering.
// FWHT_4096 = F16(bits 0-3) (x) F16(bits 4-7) (x) F16(bits 8-11).
// One CTA per row, 256 threads, 16 elems/thread, two smem exchanges.
// R6: smem WRITE sides vectorized to STS.128 with quad-granularity XOR
// swizzles (conflict-free both directions), 8 CTAs/SM.

#define FWHT_N  4096
#define NP      272          // row pitch in floats; 272 % 32 == 16

__device__ __forceinline__ void fwht16(float v[16]) {
#pragma unroll
    for (int h = 1; h < 16; h <<= 1) {
#pragma unroll
        for (int i = 0; i < 16; i++) {
            if ((i & h) == 0) {
                float a = v[i];
                float b = v[i + h];
                v[i]     = a + b;
                v[i + h] = a - b;
            }
        }
    }
}

__global__ __launch_bounds__(256, 8)
void HadamardTransform_68891275428167_kernel(const float* __restrict__ x,
                                             float* __restrict__ y) {
    __shared__ __align__(16) float s[16 * NP];   // 17408 B

    const int t = threadIdx.x;                    // 0..255
    const size_t row_off = (size_t)blockIdx.x * FWHT_N;
    const float* __restrict__ xr = x + row_off;
    float* __restrict__ yr = y + row_off;

    float v[16];

    // ---- Load: thread t = (c,m) owns l (bits 0-3); 4x LDG.128, dense. ----
    {
        const float4* __restrict__ xv =
            reinterpret_cast<const float4*>(xr + t * 16);
#pragma unroll
        for (int j = 0; j < 4; j++) {
            float4 f = xv[j];
            v[4 * j + 0] = f.x;
            v[4 * j + 1] = f.y;
            v[4 * j + 2] = f.z;
            v[4 * j + 3] = f.w;
        }
    }
    fwht16(v);   // bits 0-3

    const int c_w1 = t >> 4;       // as writer of exchange 1
    const int m_w1 = t & 15;

    // ---- Exchange 1 ----
    // addr1(c,m,l) = c*NP + m*16 + ((l>>2) ^ ((m>>1)&3))*4 + (l&3)
    // Write: 4x STS.128 per thread, conflict-free.
    {
        const int sm = (m_w1 >> 1) & 3;
        float4* dst = reinterpret_cast<float4*>(s + c_w1 * NP + m_w1 * 16);
#pragma unroll
        for (int cj = 0; cj < 4; cj++)
            dst[cj ^ sm] = make_float4(v[4 * cj + 0], v[4 * cj + 1],
                                       v[4 * cj + 2], v[4 * cj + 3]);
    }
    __syncthreads();
    // Read: thread (c,l) gathers over m; 16x LDS.32, conflict-free.
    {
        const int c = t >> 4;
        const int l = t & 15;
        const int cj = l >> 2;
        const int li = l & 3;
        const float* base = s + c * NP + li;
#pragma unroll
        for (int m = 0; m < 16; m++)
            v[m] = base[m * 16 + ((cj ^ ((m >> 1) & 3)) << 2)];
    }
    fwht16(v);   // bits 4-7

    __syncthreads();   // all exchange-1 reads done before overwrite

    // ---- Exchange 2 ----
    // addr2(c,m,l) = l*NP + c*16 + ((m>>2) ^ ((l>>1)&3))*4
    //                           + ((m&3) ^ (((l>>3)&1)<<1))
    // Write: thread (c,l) holds v[m]; 4x STS.128 with half-swap for l>=8.
    {
        const int c = t >> 4;
        const int l = t & 15;
        const int sm2 = (l >> 1) & 3;
        const bool xsw = (l & 8) != 0;
        float4* dst = reinterpret_cast<float4*>(s + l * NP + c * 16);
#pragma unroll
        for (int mq = 0; mq < 4; mq++) {
            float4 F;
            if (xsw)
                F = make_float4(v[4 * mq + 2], v[4 * mq + 3],
                                v[4 * mq + 0], v[4 * mq + 1]);
            else
                F = make_float4(v[4 * mq + 0], v[4 * mq + 1],
                                v[4 * mq + 2], v[4 * mq + 3]);
            dst[mq ^ sm2] = F;
        }
    }
    __syncthreads();
    // Read: thread (m,l) gathers over k = bits 8-11; 16x LDS.32, conflict-free.
    {
        const int m = t >> 4;
        const int l = t & 15;
        const int Q = (((m >> 2) ^ ((l >> 1) & 3)) << 2);
        const int P = (m & 3) ^ (((l >> 3) & 1) << 1);
        const float* base = s + l * NP + Q + P;
#pragma unroll
        for (int k = 0; k < 16; k++)
            v[k] = base[k * 16];
    }
    fwht16(v);   // bits 8-11

    // ---- Store: thread t writes y[k*256 + t]; dense 1 wf/instr. ----
#pragma unroll
    for (int k = 0; k < 16; k++)
        yr[k * 256 + t] = v[k];
}

extern "C" void kernel_launch(void* const* d_in, const int* in_sizes, int n_in,
                              void* d_out, int out_size) {
    const float* x = (const float*)d_in[0];
    float* y = (float*)d_out;

    const int rows = in_sizes[0] / FWHT_N;   // 16384
    HadamardTransform_68891275428167_kernel<<<rows, 256>>>(x, y);
}